// round 1
// baseline (speedup 1.0000x reference)
#include <cuda_runtime.h>

// Problem constants
constexpr int Bn = 4, T = 1024, Cc = 512, Hh = 8, HD = 64;
constexpr int M = Bn * T;          // 4096 rows for projections
constexpr int Kdim = Cc;           // 512
constexpr int Ndim = Cc;           // 512
constexpr float SCALE = 0.125f;    // 1/sqrt(64)

// Scratch (device globals: no allocations allowed)
__device__ float g_q[Bn * Hh * T * HD];
__device__ float g_k[Bn * Hh * T * HD];
__device__ float g_v[Bn * Hh * T * HD];
__device__ float g_y[Bn * T * Cc];

// ---------------------------------------------------------------------------
// SGEMM core: out = A @ W^T + bias.  A: [M,512] row-major, W: [N,512] row-major.
// Block tile 128x128, K-tile 16, 256 threads, 8x8 register tile per thread.
// headout=1 writes into [B,H,T,HD] layout (for q/k/v), else row-major [M,N].
// ---------------------------------------------------------------------------
__device__ __forceinline__ void gemm_body(const float* __restrict__ A,
                                          const float* __restrict__ W,
                                          const float* __restrict__ bias,
                                          float* __restrict__ out,
                                          int headout)
{
    __shared__ float As[16][128];
    __shared__ float Ws[16][128];

    const int tid = threadIdx.x;
    const int tx = tid & 15;
    const int ty = tid >> 4;
    const int m0 = blockIdx.y * 128;
    const int n0 = blockIdx.x * 128;

    float acc[8][8];
#pragma unroll
    for (int i = 0; i < 8; ++i)
#pragma unroll
        for (int j = 0; j < 8; ++j) acc[i][j] = 0.f;

    const float* Ap = A + (size_t)m0 * Kdim;
    const float* Wp = W + (size_t)n0 * Kdim;

    for (int k0 = 0; k0 < Kdim; k0 += 16) {
        // Load 128x16 tiles of A and W (transposed into k-major smem)
#pragma unroll
        for (int it = 0; it < 2; ++it) {
            int li  = tid * 2 + it;     // 0..511 float4 index
            int row = li >> 2;          // 0..127
            int cv  = li & 3;           // float4 within 16-wide k
            float4 a = *reinterpret_cast<const float4*>(Ap + (size_t)row * Kdim + k0 + cv * 4);
            As[cv * 4 + 0][row] = a.x; As[cv * 4 + 1][row] = a.y;
            As[cv * 4 + 2][row] = a.z; As[cv * 4 + 3][row] = a.w;
            float4 w = *reinterpret_cast<const float4*>(Wp + (size_t)row * Kdim + k0 + cv * 4);
            Ws[cv * 4 + 0][row] = w.x; Ws[cv * 4 + 1][row] = w.y;
            Ws[cv * 4 + 2][row] = w.z; Ws[cv * 4 + 3][row] = w.w;
        }
        __syncthreads();

#pragma unroll
        for (int k = 0; k < 16; ++k) {
            float a[8], w[8];
            *(float4*)&a[0] = *(float4*)&As[k][ty * 8];
            *(float4*)&a[4] = *(float4*)&As[k][ty * 8 + 4];
            *(float4*)&w[0] = *(float4*)&Ws[k][tx * 8];
            *(float4*)&w[4] = *(float4*)&Ws[k][tx * 8 + 4];
#pragma unroll
            for (int i = 0; i < 8; ++i)
#pragma unroll
                for (int j = 0; j < 8; ++j)
                    acc[i][j] += a[i] * w[j];
        }
        __syncthreads();
    }

    // Epilogue
#pragma unroll
    for (int i = 0; i < 8; ++i) {
        int m = m0 + ty * 8 + i;
#pragma unroll
        for (int j = 0; j < 8; ++j) {
            int n = n0 + tx * 8 + j;
            float v = acc[i][j] + bias[n];
            if (headout) {
                int b  = m >> 10;     // / T
                int t  = m & 1023;
                int h  = n >> 6;      // / HD
                int hd = n & 63;
                out[(((size_t)(b * Hh + h) * T) + t) * HD + hd] = v;
            } else {
                out[(size_t)m * Ndim + n] = v;
            }
        }
    }
}

__global__ __launch_bounds__(256)
void qkv_kernel(const float* __restrict__ x,
                const float* __restrict__ Wq, const float* __restrict__ bq,
                const float* __restrict__ Wk, const float* __restrict__ bk,
                const float* __restrict__ Wv, const float* __restrict__ bv)
{
    const float* W; const float* bb; float* o;
    if (blockIdx.z == 0)      { W = Wq; bb = bq; o = g_q; }
    else if (blockIdx.z == 1) { W = Wk; bb = bk; o = g_k; }
    else                      { W = Wv; bb = bv; o = g_v; }
    gemm_body(x, W, bb, o, 1);
}

__global__ __launch_bounds__(256)
void proj_kernel(const float* __restrict__ Wp, const float* __restrict__ bp,
                 float* __restrict__ out)
{
    gemm_body(g_y, Wp, bp, out, 0);
}

// ---------------------------------------------------------------------------
// Attention: one thread = one query row (q, o accumulator in registers),
// K/V staged per 64-key tile in smem (broadcast reads), online softmax with
// 16-key subchunks. Mask: j<=i causal AND (j % 16 != 15). Bias for i,j < 512:
// attn_bias[h, i/8, j/8].
// ---------------------------------------------------------------------------
constexpr int BQ = 128;   // queries per block
constexpr int KT = 64;    // keys per smem tile

__global__ __launch_bounds__(128)
void attn_kernel(const float* __restrict__ attn_bias)
{
    __shared__ float Ks[KT][HD];
    __shared__ float Vs[KT][HD];

    const int qt  = blockIdx.x;
    const int h   = blockIdx.y;
    const int b   = blockIdx.z;
    const int tid = threadIdx.x;
    const int iq  = qt * BQ + tid;               // global query index

    const size_t bh_off = (size_t)(b * Hh + h) * T * HD;
    const float* qbase = g_q + bh_off + (size_t)iq * HD;
    const float* kb    = g_k + bh_off;
    const float* vb    = g_v + bh_off;
    const float* bh    = attn_bias + h * 64 * 64;

    float qr[HD];
#pragma unroll
    for (int d4 = 0; d4 < HD / 4; ++d4)
        *(float4*)&qr[d4 * 4] = *(const float4*)(qbase + d4 * 4);

    float o[HD];
#pragma unroll
    for (int d = 0; d < HD; ++d) o[d] = 0.f;
    float mrun = -1e30f, lrun = 0.f;

    const int nkt = qt * (BQ / KT) + (BQ / KT);  // key tiles covering causal span

    for (int kt = 0; kt < nkt; ++kt) {
        const int kbase = kt * KT;
        // Stage K and V tiles (coalesced float4 copies)
        for (int li = tid; li < KT * HD / 4; li += 128) {
            ((float4*)&Ks[0][0])[li] = ((const float4*)(kb + (size_t)kbase * HD))[li];
            ((float4*)&Vs[0][0])[li] = ((const float4*)(vb + (size_t)kbase * HD))[li];
        }
        __syncthreads();

#pragma unroll
        for (int sc = 0; sc < KT / 16; ++sc) {
            float s[16];
#pragma unroll
            for (int kk = 0; kk < 16; ++kk) {
                float acc = 0.f;
#pragma unroll
                for (int d = 0; d < HD; ++d)
                    acc += qr[d] * Ks[sc * 16 + kk][d];
                int j = kbase + sc * 16 + kk;
                acc *= SCALE;
                if (iq < 512 && j < 512)
                    acc += bh[(iq >> 3) * 64 + (j >> 3)];
                if (j > iq || (j & 15) == 15)
                    acc = -1e30f;
                s[kk] = acc;
            }
            float mt = s[0];
#pragma unroll
            for (int kk = 1; kk < 16; ++kk) mt = fmaxf(mt, s[kk]);
            float mnew  = fmaxf(mrun, mt);
            float alpha = __expf(mrun - mnew);
            lrun *= alpha;
#pragma unroll
            for (int d = 0; d < HD; ++d) o[d] *= alpha;
#pragma unroll
            for (int kk = 0; kk < 16; ++kk) {
                s[kk] = __expf(s[kk] - mnew);
                lrun += s[kk];
            }
#pragma unroll
            for (int kk = 0; kk < 16; ++kk)
#pragma unroll
                for (int d = 0; d < HD; ++d)
                    o[d] += s[kk] * Vs[sc * 16 + kk][d];
            mrun = mnew;
        }
        __syncthreads();
    }

    const float inv = 1.f / lrun;
#pragma unroll
    for (int d = 0; d < HD; ++d) o[d] *= inv;

    float* yout = g_y + ((size_t)(b * T + iq)) * Cc + h * HD;
#pragma unroll
    for (int d4 = 0; d4 < HD / 4; ++d4)
        *(float4*)(yout + d4 * 4) = *(float4*)&o[d4 * 4];
}

// ---------------------------------------------------------------------------
extern "C" void kernel_launch(void* const* d_in, const int* in_sizes, int n_in,
                              void* d_out, int out_size)
{
    const float* x         = (const float*)d_in[0];
    const float* attn_bias = (const float*)d_in[1];
    const float* Wq        = (const float*)d_in[2];
    const float* bq        = (const float*)d_in[3];
    const float* Wk        = (const float*)d_in[4];
    const float* bk        = (const float*)d_in[5];
    const float* Wv        = (const float*)d_in[6];
    const float* bv        = (const float*)d_in[7];
    const float* Wp        = (const float*)d_in[8];
    const float* bp        = (const float*)d_in[9];
    float* out             = (float*)d_out;

    // Fused QKV projections: grid.z selects q/k/v
    dim3 ggrid(Ndim / 128, M / 128, 3);
    qkv_kernel<<<ggrid, 256>>>(x, Wq, bq, Wk, bk, Wv, bv);

    // Attention
    dim3 agrid(T / BQ, Hh, Bn);
    attn_kernel<<<agrid, 128>>>(attn_bias);

    // Output projection
    dim3 pgrid(Ndim / 128, M / 128, 1);
    proj_kernel<<<pgrid, 256>>>(Wp, bp, out);
}

// round 3
// speedup vs baseline: 1.7773x; 1.7773x over previous
#include <cuda_runtime.h>

// Problem constants
constexpr int Bn = 4, T = 1024, Cc = 512, Hh = 8, HD = 64;
constexpr int Kdim = Cc;           // 512
constexpr int Ndim = Cc;           // 512
constexpr float SCALE = 0.125f;    // 1/sqrt(64)

// Scratch (device globals: no allocations allowed)
__device__ float g_q[Bn * Hh * T * HD];
__device__ float g_k[Bn * Hh * T * HD];
__device__ float g_v[Bn * Hh * T * HD];
__device__ float g_y[Bn * T * Cc];

// ---------------------------------------------------------------------------
// SGEMM: out = A @ W^T + bias.  A: [M,512] rm, W: [N,512] rm.
// 128x128 block tile, K-tile 16, 256 threads, 8x8 reg tile (4+4 split),
// register-prefetch pipeline on global loads.
// ---------------------------------------------------------------------------
__device__ __forceinline__ void gemm_body(const float* __restrict__ A,
                                          const float* __restrict__ W,
                                          const float* __restrict__ bias,
                                          float* __restrict__ out,
                                          int headout)
{
    __shared__ float As[16][128];
    __shared__ float Ws[16][128];

    const int tid = threadIdx.x;
    const int tx = tid & 15;
    const int ty = tid >> 4;
    const int m0 = blockIdx.y * 128;
    const int n0 = blockIdx.x * 128;
    const int lrow = tid >> 1;
    const int lcv  = (tid & 1) * 2;   // 0 or 2 (float4 slot)

    const float* Ap = A + (size_t)(m0 + lrow) * Kdim + lcv * 4;
    const float* Wp = W + (size_t)(n0 + lrow) * Kdim + lcv * 4;

    float acc[8][8];
#pragma unroll
    for (int i = 0; i < 8; ++i)
#pragma unroll
        for (int j = 0; j < 8; ++j) acc[i][j] = 0.f;

    float4 pa0 = *(const float4*)(Ap + 0);
    float4 pa1 = *(const float4*)(Ap + 4);
    float4 pw0 = *(const float4*)(Wp + 0);
    float4 pw1 = *(const float4*)(Wp + 4);

#define STORE_TILES(A0, A1, W0, W1) do {                                       \
    As[lcv*4+0][lrow]=(A0).x; As[lcv*4+1][lrow]=(A0).y;                        \
    As[lcv*4+2][lrow]=(A0).z; As[lcv*4+3][lrow]=(A0).w;                        \
    As[lcv*4+4][lrow]=(A1).x; As[lcv*4+5][lrow]=(A1).y;                        \
    As[lcv*4+6][lrow]=(A1).z; As[lcv*4+7][lrow]=(A1).w;                        \
    Ws[lcv*4+0][lrow]=(W0).x; Ws[lcv*4+1][lrow]=(W0).y;                        \
    Ws[lcv*4+2][lrow]=(W0).z; Ws[lcv*4+3][lrow]=(W0).w;                        \
    Ws[lcv*4+4][lrow]=(W1).x; Ws[lcv*4+5][lrow]=(W1).y;                        \
    Ws[lcv*4+6][lrow]=(W1).z; Ws[lcv*4+7][lrow]=(W1).w;                        \
} while (0)

#define COMPUTE16() do {                                                       \
    _Pragma("unroll")                                                          \
    for (int k = 0; k < 16; ++k) {                                             \
        float av[8], wv[8];                                                    \
        *(float4*)&av[0] = *(float4*)&As[k][ty * 4];                           \
        *(float4*)&av[4] = *(float4*)&As[k][64 + ty * 4];                      \
        *(float4*)&wv[0] = *(float4*)&Ws[k][tx * 4];                           \
        *(float4*)&wv[4] = *(float4*)&Ws[k][64 + tx * 4];                      \
        _Pragma("unroll")                                                      \
        for (int i = 0; i < 8; ++i)                                            \
            _Pragma("unroll")                                                  \
            for (int j = 0; j < 8; ++j)                                        \
                acc[i][j] += av[i] * wv[j];                                    \
    }                                                                          \
} while (0)

    STORE_TILES(pa0, pa1, pw0, pw1);

    for (int k0 = 16; k0 < Kdim; k0 += 16) {
        __syncthreads();
        float4 na0 = *(const float4*)(Ap + k0);
        float4 na1 = *(const float4*)(Ap + k0 + 4);
        float4 nw0 = *(const float4*)(Wp + k0);
        float4 nw1 = *(const float4*)(Wp + k0 + 4);
        COMPUTE16();
        __syncthreads();
        STORE_TILES(na0, na1, nw0, nw1);
    }
    __syncthreads();
    COMPUTE16();

    // Epilogue
#pragma unroll
    for (int i = 0; i < 8; ++i) {
        int m = m0 + (i < 4 ? ty * 4 + i : 64 + ty * 4 + (i - 4));
#pragma unroll
        for (int j = 0; j < 8; ++j) {
            int n = n0 + (j < 4 ? tx * 4 + j : 64 + tx * 4 + (j - 4));
            float v = acc[i][j] + bias[n];
            if (headout) {
                int b  = m >> 10;
                int t  = m & 1023;
                int h  = n >> 6;
                int hd = n & 63;
                out[(((size_t)(b * Hh + h) * T) + t) * HD + hd] = v;
            } else {
                out[(size_t)m * Ndim + n] = v;
            }
        }
    }
#undef STORE_TILES
#undef COMPUTE16
}

__global__ __launch_bounds__(256)
void qkv_kernel(const float* __restrict__ x,
                const float* __restrict__ Wq, const float* __restrict__ bq,
                const float* __restrict__ Wk, const float* __restrict__ bk,
                const float* __restrict__ Wv, const float* __restrict__ bv)
{
    const float* W; const float* bb; float* o;
    if (blockIdx.z == 0)      { W = Wq; bb = bq; o = g_q; }
    else if (blockIdx.z == 1) { W = Wk; bb = bk; o = g_k; }
    else                      { W = Wv; bb = bv; o = g_v; }
    gemm_body(x, W, bb, o, 1);
}

__global__ __launch_bounds__(256)
void proj_kernel(const float* __restrict__ Wp, const float* __restrict__ bp,
                 float* __restrict__ out)
{
    gemm_body(g_y, Wp, bp, out, 0);
}

// ---------------------------------------------------------------------------
// Tiled flash attention: 64 queries x 64 keys per tile, 128 threads,
// 4x8 register tile per thread. Q/K staged transposed ([d][t]) for
// conflict-free outer-product LDS.128; V row-major; P broadcast via shfl.
// ---------------------------------------------------------------------------
__global__ __launch_bounds__(128)
void attn_kernel(const float* __restrict__ attn_bias)
{
    __shared__ float Qs[64][64];   // [d][row]
    __shared__ float Ks[64][64];   // [d][key]
    __shared__ float Vs[64][64];   // [key][d]

    const int qt  = gridDim.x - 1 - blockIdx.x;  // long blocks launch first
    const int h   = blockIdx.y;
    const int b   = blockIdx.z;
    const int tid = threadIdx.x;
    const int tx  = tid & 7;     // 8-wide: key cols / d cols
    const int ty  = tid >> 3;    // 16-tall: query rows
    const int lane = tid & 31;
    const int q0  = qt * 64;

    const size_t bh = (size_t)(b * Hh + h) * T * HD;
    const float* qp = g_q + bh;
    const float* kp = g_k + bh;
    const float* vp = g_v + bh;
    const float* bias_h = attn_bias + h * 64 * 64;

    // Stage Q transposed: Qs[d][row]
#pragma unroll
    for (int it = 0; it < 8; ++it) {
        int li = it * 128 + tid;
        int t = li & 63, c4 = li >> 6;
        float4 v = *(const float4*)(qp + (size_t)(q0 + t) * HD + c4 * 4);
        Qs[c4 * 4 + 0][t] = v.x; Qs[c4 * 4 + 1][t] = v.y;
        Qs[c4 * 4 + 2][t] = v.z; Qs[c4 * 4 + 3][t] = v.w;
    }

    float o[4][8];
#pragma unroll
    for (int i = 0; i < 4; ++i)
#pragma unroll
        for (int j = 0; j < 8; ++j) o[i][j] = 0.f;
    float mrow[4] = {-1e30f, -1e30f, -1e30f, -1e30f};
    float lsum[4] = {0.f, 0.f, 0.f, 0.f};

    for (int kt = 0; kt <= qt; ++kt) {
        const int kbase = kt * 64;
        __syncthreads();   // protect Ks/Vs from previous iteration's readers
        // Stage K transposed + V row-major
#pragma unroll
        for (int it = 0; it < 8; ++it) {
            int li = it * 128 + tid;
            int t = li & 63, c4 = li >> 6;
            float4 kv = *(const float4*)(kp + (size_t)(kbase + t) * HD + c4 * 4);
            Ks[c4 * 4 + 0][t] = kv.x; Ks[c4 * 4 + 1][t] = kv.y;
            Ks[c4 * 4 + 2][t] = kv.z; Ks[c4 * 4 + 3][t] = kv.w;
            int r = li >> 4, cc = li & 15;
            *(float4*)&Vs[r][cc * 4] =
                *(const float4*)(vp + (size_t)(kbase + r) * HD + cc * 4);
        }
        __syncthreads();

        // GEMM1: S = Q . K^T (outer product over d)
        float s[4][8];
#pragma unroll
        for (int i = 0; i < 4; ++i)
#pragma unroll
            for (int j = 0; j < 8; ++j) s[i][j] = 0.f;

#pragma unroll 16
        for (int d = 0; d < 64; ++d) {
            float4 a  = *(float4*)&Qs[d][ty * 4];
            float4 b0 = *(float4*)&Ks[d][tx * 4];
            float4 b1 = *(float4*)&Ks[d][32 + tx * 4];
            float av[4] = {a.x, a.y, a.z, a.w};
            float bv[8] = {b0.x, b0.y, b0.z, b0.w, b1.x, b1.y, b1.z, b1.w};
#pragma unroll
            for (int i = 0; i < 4; ++i)
#pragma unroll
                for (int j = 0; j < 8; ++j)
                    s[i][j] += av[i] * bv[j];
        }

        // scale + bias + mask
        const bool diag = (kt == qt);
        const bool has_bias = (q0 < 512) && (kbase < 512);
#pragma unroll
        for (int ii = 0; ii < 4; ++ii) {
            int r = q0 + ty * 4 + ii;
#pragma unroll
            for (int jj = 0; jj < 8; ++jj) {
                int col = (jj < 4 ? tx * 4 + jj : 32 + tx * 4 + (jj - 4));
                int jg = kbase + col;
                float v = s[ii][jj] * SCALE;
                if (has_bias) v += bias_h[(r >> 3) * 64 + (jg >> 3)];
                if ((jg & 15) == 15 || (diag && jg > r)) v = -1e30f;
                s[ii][jj] = v;
            }
        }

        // online softmax (row reductions across the 8 tx lanes)
#pragma unroll
        for (int ii = 0; ii < 4; ++ii) {
            float mt = s[ii][0];
#pragma unroll
            for (int jj = 1; jj < 8; ++jj) mt = fmaxf(mt, s[ii][jj]);
            mt = fmaxf(mt, __shfl_xor_sync(0xffffffffu, mt, 1));
            mt = fmaxf(mt, __shfl_xor_sync(0xffffffffu, mt, 2));
            mt = fmaxf(mt, __shfl_xor_sync(0xffffffffu, mt, 4));
            float mnew  = fmaxf(mrow[ii], mt);
            float alpha = __expf(mrow[ii] - mnew);
            mrow[ii] = mnew;
            float rs = 0.f;
#pragma unroll
            for (int jj = 0; jj < 8; ++jj) {
                s[ii][jj] = __expf(s[ii][jj] - mnew);
                rs += s[ii][jj];
            }
            rs += __shfl_xor_sync(0xffffffffu, rs, 1);
            rs += __shfl_xor_sync(0xffffffffu, rs, 2);
            rs += __shfl_xor_sync(0xffffffffu, rs, 4);
            lsum[ii] = lsum[ii] * alpha + rs;
#pragma unroll
            for (int jj = 0; jj < 8; ++jj) o[ii][jj] *= alpha;
        }

        // GEMM2: O += P . V  (P broadcast over the 8 tx lanes via shfl)
#pragma unroll
        for (int k = 0; k < 64; ++k) {
            const int owner = (k & 31) >> 2;
            const int slot  = (k & 3) + (k >= 32 ? 4 : 0);
            const int src   = (lane & 24) | owner;
            float4 v0 = *(float4*)&Vs[k][tx * 4];
            float4 v1 = *(float4*)&Vs[k][32 + tx * 4];
            float p0 = __shfl_sync(0xffffffffu, s[0][slot], src);
            float p1 = __shfl_sync(0xffffffffu, s[1][slot], src);
            float p2 = __shfl_sync(0xffffffffu, s[2][slot], src);
            float p3 = __shfl_sync(0xffffffffu, s[3][slot], src);
            float bv[8] = {v0.x, v0.y, v0.z, v0.w, v1.x, v1.y, v1.z, v1.w};
            float pv[4] = {p0, p1, p2, p3};
#pragma unroll
            for (int i = 0; i < 4; ++i)
#pragma unroll
                for (int j = 0; j < 8; ++j)
                    o[i][j] += pv[i] * bv[j];
        }
    }

    // finalize + write y
#pragma unroll
    for (int ii = 0; ii < 4; ++ii) {
        float inv = 1.f / lsum[ii];
#pragma unroll
        for (int jj = 0; jj < 8; ++jj) o[ii][jj] *= inv;
        int r = q0 + ty * 4 + ii;
        float* yout = g_y + ((size_t)(b * T + r)) * Cc + h * HD;
        *(float4*)(yout + tx * 4)      = *(float4*)&o[ii][0];
        *(float4*)(yout + 32 + tx * 4) = *(float4*)&o[ii][4];
    }
}

// ---------------------------------------------------------------------------
extern "C" void kernel_launch(void* const* d_in, const int* in_sizes, int n_in,
                              void* d_out, int out_size)
{
    const float* x         = (const float*)d_in[0];
    const float* attn_bias = (const float*)d_in[1];
    const float* Wq        = (const float*)d_in[2];
    const float* bq        = (const float*)d_in[3];
    const float* Wk        = (const float*)d_in[4];
    const float* bk        = (const float*)d_in[5];
    const float* Wv        = (const float*)d_in[6];
    const float* bv        = (const float*)d_in[7];
    const float* Wp        = (const float*)d_in[8];
    const float* bp        = (const float*)d_in[9];
    float* out             = (float*)d_out;

    dim3 ggrid(Ndim / 128, (Bn * T) / 128, 3);
    qkv_kernel<<<ggrid, 256>>>(x, Wq, bq, Wk, bk, Wv, bv);

    dim3 agrid(T / 64, Hh, Bn);
    attn_kernel<<<agrid, 128>>>(attn_bias);

    dim3 pgrid(Ndim / 128, (Bn * T) / 128, 1);
    proj_kernel<<<pgrid, 256>>>(Wp, bp, out);
}